// round 1
// baseline (speedup 1.0000x reference)
#include <cuda_runtime.h>

// ---------------- problem constants ----------------
constexpr int  BATCH = 16;
constexpr int  CCH   = 1024;   // C
constexpr int  CI    = 256;    // inter channels
constexpr int  NPIX  = 2048;   // H*W
constexpr float BN_EPS = 1e-5f;

// ---------------- scratch (device globals; no allocation allowed) ----------------
// layout: [0]=theta, [1]=phi, [2]=g ; each [BATCH][CI][NPIX]
__device__ float g_tpg [3L * BATCH * CI * NPIX];            // ~100.7 MB
__device__ float g_attn[(long)BATCH * NPIX * NPIX];         // ~268 MB
__device__ float g_y   [(long)BATCH * NPIX * CI];           // ~33.5 MB  (Y[n][o])

// ---------------- f32x2 helpers (Blackwell packed fp32) ----------------
__device__ __forceinline__ unsigned long long pack2(float lo, float hi) {
    unsigned long long r;
    asm("mov.b64 %0, {%1, %2};" : "=l"(r) : "f"(lo), "f"(hi));
    return r;
}
__device__ __forceinline__ void unpack2(unsigned long long v, float& lo, float& hi) {
    asm("mov.b64 {%0, %1}, %2;" : "=f"(lo), "=f"(hi) : "l"(v));
}
__device__ __forceinline__ void fma2(unsigned long long& d, unsigned long long a, unsigned long long b) {
    asm("fma.rn.f32x2 %0, %1, %2, %0;" : "+l"(d) : "l"(a), "l"(b));
}

// ---------------- generic batched GEMM ----------------
// C[m][n] = sum_k opA(m,k) * opB(k,n)     (per batch, blockIdx.z)
//  AT=false: A element (m,k) at A[m*lda + k]     (row-major MxK)
//  AT=true : A element (m,k) at A[k*lda + m]     (K-major, i.e. A^T stored KxM)
//  BT=false: B element (k,n) at B[k*ldb + n]     (row-major KxN)
//  BT=true : B element (k,n) at B[n*ldb + k]     (N-major, i.e. B^T stored NxK)
// EPI: 0 = none, 1 = +bias[m], 2 = bias+BN+residual (final layer)
#define BMT 128
#define BNT 128
#define BKT 8
#define TM  8
#define TN  8

template<bool AT, bool BT, int EPI>
__global__ void __launch_bounds__(256, 2)
gemm_k(const float* __restrict__ Ag, const float* __restrict__ Bg, float* __restrict__ Cg,
       int K, int lda, int ldb, int ldc,
       long sA, long sB, long sC,
       const float* __restrict__ bias,
       const float* __restrict__ wb,  const float* __restrict__ gma,
       const float* __restrict__ bta, const float* __restrict__ mean,
       const float* __restrict__ var, const float* __restrict__ resid, long sRes)
{
    const float* A = Ag + (long)blockIdx.z * sA;
    const float* B = Bg + (long)blockIdx.z * sB;
    float*       C = Cg + (long)blockIdx.z * sC;
    const float* res = (EPI == 2) ? (resid + (long)blockIdx.z * sRes) : nullptr;

    // A tile stored lane-duplicated as f32x2 pairs -> inner loop is pure LDS.128 + FFMA2
    __shared__ unsigned long long As2[BKT][BMT];   // 8 KB
    __shared__ float              Bs [BKT][BNT];   // 4 KB

    const int tid = threadIdx.x;
    const int tx  = tid & 15;       // 16 cols of threads
    const int ty  = tid >> 4;       // 16 rows of threads
    const int m0  = blockIdx.y * BMT;
    const int n0  = blockIdx.x * BNT;

    unsigned long long acc[TM][TN / 2];
#pragma unroll
    for (int i = 0; i < TM; i++)
#pragma unroll
        for (int j = 0; j < TN / 2; j++) acc[i][j] = 0ULL;

    for (int k0 = 0; k0 < K; k0 += BKT) {
        // ---- load A tile (duplicated into pairs) ----
        if (!AT) {
            const int row = tid >> 1, cg = (tid & 1) * 4;
            float4 v = *(const float4*)(A + (long)(m0 + row) * lda + (k0 + cg));
            As2[cg + 0][row] = pack2(v.x, v.x);
            As2[cg + 1][row] = pack2(v.y, v.y);
            As2[cg + 2][row] = pack2(v.z, v.z);
            As2[cg + 3][row] = pack2(v.w, v.w);
        } else {
            const int kk = tid >> 5, m4 = (tid & 31) * 4;
            float4 v = *(const float4*)(A + (long)(k0 + kk) * lda + (m0 + m4));
            As2[kk][m4 + 0] = pack2(v.x, v.x);
            As2[kk][m4 + 1] = pack2(v.y, v.y);
            As2[kk][m4 + 2] = pack2(v.z, v.z);
            As2[kk][m4 + 3] = pack2(v.w, v.w);
        }
        // ---- load B tile ----
        if (!BT) {
            const int kk = tid >> 5, n4 = (tid & 31) * 4;
            *(float4*)&Bs[kk][n4] = *(const float4*)(B + (long)(k0 + kk) * ldb + (n0 + n4));
        } else {
            const int row = tid >> 1, cg = (tid & 1) * 4;
            float4 v = *(const float4*)(B + (long)(n0 + row) * ldb + (k0 + cg));
            Bs[cg + 0][row] = v.x;
            Bs[cg + 1][row] = v.y;
            Bs[cg + 2][row] = v.z;
            Bs[cg + 3][row] = v.w;
        }
        __syncthreads();

#pragma unroll
        for (int k = 0; k < BKT; k++) {
            ulonglong2 p0 = *(const ulonglong2*)&As2[k][ty * TM + 0];
            ulonglong2 p1 = *(const ulonglong2*)&As2[k][ty * TM + 2];
            ulonglong2 p2 = *(const ulonglong2*)&As2[k][ty * TM + 4];
            ulonglong2 p3 = *(const ulonglong2*)&As2[k][ty * TM + 6];
            unsigned long long a2[TM] = {p0.x, p0.y, p1.x, p1.y, p2.x, p2.y, p3.x, p3.y};
            ulonglong2 q0 = *(const ulonglong2*)&Bs[k][tx * TN + 0];
            ulonglong2 q1 = *(const ulonglong2*)&Bs[k][tx * TN + 4];
            unsigned long long bp[TN / 2] = {q0.x, q0.y, q1.x, q1.y};
#pragma unroll
            for (int i = 0; i < TM; i++)
#pragma unroll
                for (int j = 0; j < TN / 2; j++)
                    fma2(acc[i][j], a2[i], bp[j]);
        }
        __syncthreads();
    }

    // ---- epilogue ----
    float cv[TM][TN];
#pragma unroll
    for (int i = 0; i < TM; i++)
#pragma unroll
        for (int j = 0; j < TN / 2; j++)
            unpack2(acc[i][j], cv[i][2 * j], cv[i][2 * j + 1]);

#pragma unroll
    for (int i = 0; i < TM; i++) {
        const int m = m0 + ty * TM + i;
        float add = 0.f, mul = 1.f, post = 0.f;
        if (EPI == 1) add = bias[m];
        if (EPI == 2) {
            mul  = gma[m] * rsqrtf(var[m] + BN_EPS);
            add  = wb[m] - mean[m];
            post = bta[m];
        }
        const long base = (long)m * ldc + n0 + tx * TN;
        float o[TN];
#pragma unroll
        for (int j = 0; j < TN; j++) o[j] = (cv[i][j] + add) * mul + post;
        if (EPI == 2) {
            float4 r0 = *(const float4*)(res + base);
            float4 r1 = *(const float4*)(res + base + 4);
            o[0] += r0.x; o[1] += r0.y; o[2] += r0.z; o[3] += r0.w;
            o[4] += r1.x; o[5] += r1.y; o[6] += r1.z; o[7] += r1.w;
        }
        *(float4*)(C + base)     = make_float4(o[0], o[1], o[2], o[3]);
        *(float4*)(C + base + 4) = make_float4(o[4], o[5], o[6], o[7]);
    }
}

// ---------------- row softmax over the 2048-wide attention rows ----------------
__global__ void softmax_rows(float* __restrict__ P, int N)
{
    const long row = (long)blockIdx.y * gridDim.x + blockIdx.x;  // b*N + n
    float* p = P + row * (long)N;
    const int tid  = threadIdx.x;          // 256 threads, 8 elems each
    const int lane = tid & 31, warp = tid >> 5;

    float4 u0 = *(const float4*)(p + tid * 8);
    float4 u1 = *(const float4*)(p + tid * 8 + 4);
    float v[8] = {u0.x, u0.y, u0.z, u0.w, u1.x, u1.y, u1.z, u1.w};

    __shared__ float red[8];
    float mx = v[0];
#pragma unroll
    for (int i = 1; i < 8; i++) mx = fmaxf(mx, v[i]);
#pragma unroll
    for (int o = 16; o; o >>= 1) mx = fmaxf(mx, __shfl_xor_sync(0xffffffffu, mx, o));
    if (lane == 0) red[warp] = mx;
    __syncthreads();
    mx = red[0];
#pragma unroll
    for (int w = 1; w < 8; w++) mx = fmaxf(mx, red[w]);

    float s = 0.f;
#pragma unroll
    for (int i = 0; i < 8; i++) { v[i] = __expf(v[i] - mx); s += v[i]; }
#pragma unroll
    for (int o = 16; o; o >>= 1) s += __shfl_xor_sync(0xffffffffu, s, o);
    __syncthreads();
    if (lane == 0) red[warp] = s;
    __syncthreads();
    s = red[0];
#pragma unroll
    for (int w = 1; w < 8; w++) s += red[w];

    const float r = 1.0f / s;
#pragma unroll
    for (int i = 0; i < 8; i++) v[i] *= r;
    *(float4*)(p + tid * 8)     = make_float4(v[0], v[1], v[2], v[3]);
    *(float4*)(p + tid * 8 + 4) = make_float4(v[4], v[5], v[6], v[7]);
}

// ---------------- launch ----------------
extern "C" void kernel_launch(void* const* d_in, const int* in_sizes, int n_in,
                              void* d_out, int out_size)
{
    const float* x       = (const float*)d_in[0];
    const float* theta_w = (const float*)d_in[1];
    const float* theta_b = (const float*)d_in[2];
    const float* phi_w   = (const float*)d_in[3];
    const float* phi_b   = (const float*)d_in[4];
    const float* g_w     = (const float*)d_in[5];
    const float* g_b     = (const float*)d_in[6];
    const float* w_w     = (const float*)d_in[7];
    const float* w_b     = (const float*)d_in[8];
    const float* bn_g    = (const float*)d_in[9];
    const float* bn_b    = (const float*)d_in[10];
    const float* bn_m    = (const float*)d_in[11];
    const float* bn_v    = (const float*)d_in[12];
    float* out = (float*)d_out;

    float *tpg, *attn, *y;
    cudaGetSymbolAddress((void**)&tpg,  g_tpg);
    cudaGetSymbolAddress((void**)&attn, g_attn);
    cudaGetSymbolAddress((void**)&y,    g_y);

    const long projSlice = (long)BATCH * CI * NPIX;

    dim3 blk(256);

    // K1: theta/phi/g projections.  OUT[b][o][n] = W[o,:] . x[b,:,n] + bias[o]
    for (int t = 0; t < 3; t++) {
        const float* W  = (t == 0) ? theta_w : (t == 1) ? phi_w : g_w;
        const float* bb = (t == 0) ? theta_b : (t == 1) ? phi_b : g_b;
        gemm_k<false, false, 1><<<dim3(NPIX / BNT, CI / BMT, BATCH), blk>>>(
            W, x, tpg + (long)t * projSlice,
            /*K*/CCH, /*lda*/CCH, /*ldb*/NPIX, /*ldc*/NPIX,
            /*sA*/0, /*sB*/(long)CCH * NPIX, /*sC*/(long)CI * NPIX,
            bb, nullptr, nullptr, nullptr, nullptr, nullptr, nullptr, 0);
    }

    // K2: logits[b][n][m] = sum_o theta[b][o][n] * phi[b][o][m]   (A^T * B)
    gemm_k<true, false, 0><<<dim3(NPIX / BNT, NPIX / BMT, BATCH), blk>>>(
        tpg /*theta*/, tpg + projSlice /*phi*/, attn,
        /*K*/CI, /*lda*/NPIX, /*ldb*/NPIX, /*ldc*/NPIX,
        /*sA*/(long)CI * NPIX, /*sB*/(long)CI * NPIX, /*sC*/(long)NPIX * NPIX,
        nullptr, nullptr, nullptr, nullptr, nullptr, nullptr, nullptr, 0);

    // K3: row softmax (in place)
    softmax_rows<<<dim3(NPIX, BATCH), 256>>>(attn, NPIX);

    // K4: Y[b][n][o] = sum_m attn[b][n][m] * g[b][o][m]   (A * B^T)
    gemm_k<false, true, 0><<<dim3(CI / BNT, NPIX / BMT, BATCH), blk>>>(
        attn, tpg + 2 * projSlice /*g*/, y,
        /*K*/NPIX, /*lda*/NPIX, /*ldb*/NPIX, /*ldc*/CI,
        /*sA*/(long)NPIX * NPIX, /*sB*/(long)CI * NPIX, /*sC*/(long)NPIX * CI,
        nullptr, nullptr, nullptr, nullptr, nullptr, nullptr, nullptr, 0);

    // K5: out[b][c][n] = BN( sum_o w_w[c][o] * Y[b][n][o] + w_b[c] ) + x[b][c][n]
    gemm_k<false, true, 2><<<dim3(NPIX / BNT, CCH / BMT, BATCH), blk>>>(
        w_w, y, out,
        /*K*/CI, /*lda*/CI, /*ldb*/CI, /*ldc*/NPIX,
        /*sA*/0, /*sB*/(long)NPIX * CI, /*sC*/(long)CCH * NPIX,
        nullptr, w_b, bn_g, bn_b, bn_m, bn_v, x, (long)CCH * NPIX);
}

// round 4
// speedup vs baseline: 3.0708x; 3.0708x over previous
#include <cuda_runtime.h>
#include <cuda_bf16.h>
#include <cstdint>

using bf16 = __nv_bfloat16;

// ---------------- problem constants ----------------
constexpr int  BATCH = 16;
constexpr int  CCH   = 1024;   // C
constexpr int  CI    = 256;    // inter channels
constexpr int  NPIX  = 2048;   // H*W
constexpr float BN_EPS = 1e-5f;

// ---------------- scratch (device globals) ----------------
__device__ bf16 g_xT_h[(long)BATCH * NPIX * CCH];
__device__ bf16 g_xT_l[(long)BATCH * NPIX * CCH];
__device__ bf16 g_tw_h[CI * CCH];  __device__ bf16 g_tw_l[CI * CCH];
__device__ bf16 g_pw_h[CI * CCH];  __device__ bf16 g_pw_l[CI * CCH];
__device__ bf16 g_gw_h[CI * CCH];  __device__ bf16 g_gw_l[CI * CCH];
__device__ bf16 g_ww_h[CCH * CI];  __device__ bf16 g_ww_l[CCH * CI];
__device__ bf16 g_th_h[(long)BATCH * NPIX * CI];  __device__ bf16 g_th_l[(long)BATCH * NPIX * CI];
__device__ bf16 g_ph_h[(long)BATCH * NPIX * CI];  __device__ bf16 g_ph_l[(long)BATCH * NPIX * CI];
__device__ bf16 g_gv_h[(long)BATCH * CI * NPIX];  __device__ bf16 g_gv_l[(long)BATCH * CI * NPIX];
__device__ float g_logits[(long)BATCH * NPIX * NPIX];
__device__ bf16 g_at_h[(long)BATCH * NPIX * NPIX]; __device__ bf16 g_at_l[(long)BATCH * NPIX * NPIX];
__device__ bf16 g_y_h[(long)BATCH * NPIX * CI];    __device__ bf16 g_y_l[(long)BATCH * NPIX * CI];

// ---------------- small helpers ----------------
__device__ __forceinline__ uint32_t smem_u32(const void* p) {
    uint32_t a;
    asm("{ .reg .u64 t; cvta.to.shared.u64 t, %1; cvt.u32.u64 %0, t; }" : "=r"(a) : "l"(p));
    return a;
}
// swizzle for 64B rows: XOR bits[4:5] with row bits[1:2]
__device__ __forceinline__ uint32_t sw64(uint32_t x) { return x ^ ((x >> 3) & 0x30); }

__device__ __forceinline__ void cpa16(uint32_t dst, const void* src) {
    asm volatile("cp.async.cg.shared.global [%0], [%1], 16;" :: "r"(dst), "l"(src) : "memory");
}
__device__ __forceinline__ void cpa_commit() { asm volatile("cp.async.commit_group;" ::: "memory"); }

__device__ __forceinline__ void ldsm4(uint32_t& r0, uint32_t& r1, uint32_t& r2, uint32_t& r3,
                                      uint32_t a) {
    asm volatile("ldmatrix.sync.aligned.m8n8.x4.shared.b16 {%0,%1,%2,%3}, [%4];"
                 : "=r"(r0), "=r"(r1), "=r"(r2), "=r"(r3) : "r"(a));
}
__device__ __forceinline__ void mma16816(float* d, const uint32_t* a, const uint32_t* b) {
    asm volatile(
        "mma.sync.aligned.m16n8k16.row.col.f32.bf16.bf16.f32 "
        "{%0,%1,%2,%3}, {%4,%5,%6,%7}, {%8,%9}, {%0,%1,%2,%3};"
        : "+f"(d[0]), "+f"(d[1]), "+f"(d[2]), "+f"(d[3])
        : "r"(a[0]), "r"(a[1]), "r"(a[2]), "r"(a[3]), "r"(b[0]), "r"(b[1]));
}

__device__ __forceinline__ uint32_t pk2(bf16 a, bf16 b) {
    __nv_bfloat162 t = __halves2bfloat162(a, b);
    return *reinterpret_cast<uint32_t*>(&t);
}
__device__ __forceinline__ void split2(float v, bf16& h, bf16& l) {
    h = __float2bfloat16(v);
    l = __float2bfloat16(v - __bfloat162float(h));
}

// ---------------- warp-MMA split-bf16 GEMM ----------------
// D[m][n] = sum_k A[m][k]*B[n][k]; A[M,K], B[N,K] K-major split bf16 (hi+lo).
// CTA 128x128, 8 warps (2 m x 4 n), warp tile 64x32, K-chunk 32, 2-stage cp.async.
// EPI: 0=fp32 store; 1=split store + col bias; 2=split store + row bias;
//      3=split store no bias; 4=fp32 BN+residual
constexpr int STAGE_BYTES = 4 * 8192;              // Ah,Al,Bh,Bl tiles (128x32 bf16)
constexpr int GEMM_SMEM   = 2 * STAGE_BYTES + 1024;

template<int EPI>
__global__ void __launch_bounds__(256, 1)
gemm_mma(const bf16* __restrict__ Ah_, const bf16* __restrict__ Al_,
         const bf16* __restrict__ Bh_, const bf16* __restrict__ Bl_,
         int K, int lda, int ldb, int ldc,
         long sA, long sB, long sC,
         float* __restrict__ Cf, bf16* __restrict__ Ch, bf16* __restrict__ Cl,
         const float* __restrict__ bias,
         const float* __restrict__ wb,  const float* __restrict__ gma,
         const float* __restrict__ bta, const float* __restrict__ mean,
         const float* __restrict__ var, const float* __restrict__ resid, long sRes)
{
    extern __shared__ char smem[];
    const uint32_t sbase = (smem_u32(smem) + 1023) & ~1023u;

    const int tid  = threadIdx.x;
    const int lane = tid & 31;
    const int wid  = tid >> 5;
    const int m0 = blockIdx.y * 128, n0 = blockIdx.x * 128, b = blockIdx.z;
    const int m_off = (wid & 1) * 64;
    const int n_off = (wid >> 1) * 32;

    const bf16* A0h = Ah_ + (long)b * sA;
    const bf16* A0l = Al_ + (long)b * sA;
    const bf16* B0h = Bh_ + (long)b * sB;
    const bf16* B0l = Bl_ + (long)b * sB;

    // ---- loader mapping: 256 threads, 4 x 16B segs per 64B row ----
    const int lseg = tid & 3, lrow = tid >> 2;   // lrow 0..63
    auto LD = [&](int s, int k0) {
        const uint32_t st = sbase + s * STAGE_BYTES;
#pragma unroll
        for (int rr = 0; rr < 2; rr++) {
            const int r = lrow + rr * 64;
            const uint32_t sw = sw64((uint32_t)(r * 64 + lseg * 16));
            const long ao = (long)(m0 + r) * lda + k0 + lseg * 8;
            const long bo = (long)(n0 + r) * ldb + k0 + lseg * 8;
            cpa16(st +         sw, A0h + ao);
            cpa16(st +  8192 + sw, A0l + ao);
            cpa16(st + 16384 + sw, B0h + bo);
            cpa16(st + 24576 + sw, B0l + bo);
        }
        cpa_commit();
    };

    // ---- ldmatrix per-lane swizzled offsets ----
    const uint32_t swA = sw64((uint32_t)((m_off + (lane & 15)) * 64 + ((lane >> 4) & 1) * 16));
    const uint32_t swB = sw64((uint32_t)((n_off + (lane & 7) + ((lane >> 4) << 3)) * 64
                                         + ((lane >> 3) & 1) * 16));

    float d[4][4][4];
#pragma unroll
    for (int mi = 0; mi < 4; mi++)
#pragma unroll
        for (int ni = 0; ni < 4; ni++)
#pragma unroll
            for (int t = 0; t < 4; t++) d[mi][ni][t] = 0.f;

    const int nch = K >> 5;
    LD(0, 0);
    LD(1, 32);

    for (int i = 0; i < nch; i++) {
        const int s = i & 1;
        if (i + 1 < nch) asm volatile("cp.async.wait_group 1;" ::: "memory");
        else             asm volatile("cp.async.wait_group 0;" ::: "memory");
        __syncthreads();

        const uint32_t st = sbase + s * STAGE_BYTES;
#pragma unroll
        for (int kh = 0; kh < 2; kh++) {
            // kh advances the pre-swizzle column by 32B. Since the swizzle XOR mask
            // depends only on row bits (7:8) and base col bit5 is 0, the correct
            // swizzled address is obtained by XOR-ing 32, NOT adding (adding can
            // carry out of the column field into the row field).
            const uint32_t kx = (uint32_t)kh << 5;
            uint32_t aH[4][4], aL[4][4], bH[4][2], bL[4][2];
#pragma unroll
            for (int mi = 0; mi < 4; mi++) {
                ldsm4(aH[mi][0], aH[mi][1], aH[mi][2], aH[mi][3],
                      st + (swA ^ kx) + mi * 1024);
                ldsm4(aL[mi][0], aL[mi][1], aL[mi][2], aL[mi][3],
                      st + 8192 + (swA ^ kx) + mi * 1024);
            }
#pragma unroll
            for (int np = 0; np < 2; np++) {
                ldsm4(bH[np*2][0], bH[np*2][1], bH[np*2+1][0], bH[np*2+1][1],
                      st + 16384 + (swB ^ kx) + np * 1024);
                ldsm4(bL[np*2][0], bL[np*2][1], bL[np*2+1][0], bL[np*2+1][1],
                      st + 24576 + (swB ^ kx) + np * 1024);
            }
#pragma unroll
            for (int mi = 0; mi < 4; mi++)
#pragma unroll
                for (int ni = 0; ni < 4; ni++) {
                    mma16816(d[mi][ni], aH[mi], bH[ni]);
                    mma16816(d[mi][ni], aH[mi], bL[ni]);
                    mma16816(d[mi][ni], aL[mi], bH[ni]);
                }
        }
        __syncthreads();
        if (i + 2 < nch) LD(s, (i + 2) * 32);
    }

    // ---- epilogue ----
    const int rsub = lane >> 2;            // 0..7
    const int csub = (lane & 3) * 2;       // 0,2,4,6
#pragma unroll
    for (int mi = 0; mi < 4; mi++) {
#pragma unroll
        for (int h = 0; h < 2; h++) {
            const int m = m0 + m_off + mi * 16 + rsub + h * 8;
            float inv = 1.f, add = 0.f, post = 0.f;
            if (EPI == 2) add = bias[m];
            if (EPI == 4) {
                inv  = gma[m] * rsqrtf(var[m] + BN_EPS);
                add  = wb[m] - mean[m];
                post = bta[m];
            }
#pragma unroll
            for (int ni = 0; ni < 4; ni++) {
                const int col = n0 + n_off + ni * 8 + csub;
                float v0 = d[mi][ni][2 * h];
                float v1 = d[mi][ni][2 * h + 1];
                if (EPI == 1) { v0 += bias[col]; v1 += bias[col + 1]; }
                if (EPI == 2) { v0 += add; v1 += add; }
                const long base = (long)b * sC + (long)m * ldc + col;
                if (EPI == 0) {
                    *(float2*)(Cf + base) = make_float2(v0, v1);
                } else if (EPI == 4) {
                    float2 r = *(const float2*)(resid + (long)b * sRes + (long)m * ldc + col);
                    *(float2*)(Cf + base) = make_float2((v0 + add) * inv + post + r.x,
                                                        (v1 + add) * inv + post + r.y);
                } else {
                    bf16 h0, l0, h1, l1;
                    split2(v0, h0, l0);
                    split2(v1, h1, l1);
                    *(uint32_t*)(Ch + base) = pk2(h0, h1);
                    *(uint32_t*)(Cl + base) = pk2(l0, l1);
                }
            }
        }
    }
}

// ---------------- conversion kernels ----------------
__global__ void transpose_split_k(const float* __restrict__ x,
                                  bf16* __restrict__ oh, bf16* __restrict__ ol)
{
    __shared__ float t[32][33];
    const int b = blockIdx.z;
    const int n0 = blockIdx.x * 32, c0 = blockIdx.y * 32;
    const int tx = threadIdx.x, ty = threadIdx.y;
    const float* xp = x + (long)b * CCH * NPIX;
#pragma unroll
    for (int i = 0; i < 4; i++)
        t[ty + 8*i][tx] = xp[(long)(c0 + ty + 8*i) * NPIX + n0 + tx];
    __syncthreads();
    bf16* ohp = oh + (long)b * NPIX * CCH;
    bf16* olp = ol + (long)b * NPIX * CCH;
#pragma unroll
    for (int i = 0; i < 4; i++) {
        const float vv = t[tx][ty + 8*i];
        const long idx = (long)(n0 + ty + 8*i) * CCH + c0 + tx;
        bf16 h, l; split2(vv, h, l);
        ohp[idx] = h; olp[idx] = l;
    }
}

__global__ void split_arr_k(const float* __restrict__ s, bf16* __restrict__ h,
                            bf16* __restrict__ l, int n)
{
    for (int i = blockIdx.x * blockDim.x + threadIdx.x; i < n; i += gridDim.x * blockDim.x) {
        bf16 hh, ll; split2(s[i], hh, ll);
        h[i] = hh; l[i] = ll;
    }
}

// ---------------- row softmax -> split bf16 ----------------
__global__ void softmax_split(const float* __restrict__ L,
                              bf16* __restrict__ Ahi, bf16* __restrict__ Alo)
{
    const long row = (long)blockIdx.y * gridDim.x + blockIdx.x;
    const float* p = L + row * (long)NPIX;
    const int tid = threadIdx.x, lane = tid & 31, warp = tid >> 5;

    float4 u0 = *(const float4*)(p + tid * 8);
    float4 u1 = *(const float4*)(p + tid * 8 + 4);
    float v[8] = {u0.x, u0.y, u0.z, u0.w, u1.x, u1.y, u1.z, u1.w};

    __shared__ float red[8];
    float mx = v[0];
#pragma unroll
    for (int i = 1; i < 8; i++) mx = fmaxf(mx, v[i]);
#pragma unroll
    for (int o = 16; o; o >>= 1) mx = fmaxf(mx, __shfl_xor_sync(0xffffffffu, mx, o));
    if (lane == 0) red[warp] = mx;
    __syncthreads();
    mx = red[0];
#pragma unroll
    for (int w = 1; w < 8; w++) mx = fmaxf(mx, red[w]);

    float s = 0.f;
#pragma unroll
    for (int i = 0; i < 8; i++) { v[i] = __expf(v[i] - mx); s += v[i]; }
#pragma unroll
    for (int o = 16; o; o >>= 1) s += __shfl_xor_sync(0xffffffffu, s, o);
    __syncthreads();
    if (lane == 0) red[warp] = s;
    __syncthreads();
    s = red[0];
#pragma unroll
    for (int w = 1; w < 8; w++) s += red[w];

    const float r = 1.0f / s;
    uint32_t wh[4], wl[4];
#pragma unroll
    for (int t = 0; t < 4; t++) {
        bf16 h0, l0, h1, l1;
        split2(v[2*t] * r,     h0, l0);
        split2(v[2*t + 1] * r, h1, l1);
        wh[t] = pk2(h0, h1);
        wl[t] = pk2(l0, l1);
    }
    const long ob = row * (long)NPIX + tid * 8;
    *(uint4*)(Ahi + ob) = make_uint4(wh[0], wh[1], wh[2], wh[3]);
    *(uint4*)(Alo + ob) = make_uint4(wl[0], wl[1], wl[2], wl[3]);
}

// ---------------- launch ----------------
extern "C" void kernel_launch(void* const* d_in, const int* in_sizes, int n_in,
                              void* d_out, int out_size)
{
    const float* x       = (const float*)d_in[0];
    const float* theta_w = (const float*)d_in[1];
    const float* theta_b = (const float*)d_in[2];
    const float* phi_w   = (const float*)d_in[3];
    const float* phi_b   = (const float*)d_in[4];
    const float* g_w     = (const float*)d_in[5];
    const float* g_b     = (const float*)d_in[6];
    const float* w_w     = (const float*)d_in[7];
    const float* w_b     = (const float*)d_in[8];
    const float* bn_g    = (const float*)d_in[9];
    const float* bn_b    = (const float*)d_in[10];
    const float* bn_m    = (const float*)d_in[11];
    const float* bn_v    = (const float*)d_in[12];
    float* out = (float*)d_out;

    bf16 *xTh, *xTl, *twh, *twl, *pwh, *pwl, *gwh, *gwl, *wwh, *wwl;
    bf16 *thh, *thl, *phh, *phl, *gvh, *gvl, *ath, *atl, *yh, *yl;
    float* logits;
    cudaGetSymbolAddress((void**)&xTh, g_xT_h);  cudaGetSymbolAddress((void**)&xTl, g_xT_l);
    cudaGetSymbolAddress((void**)&twh, g_tw_h);  cudaGetSymbolAddress((void**)&twl, g_tw_l);
    cudaGetSymbolAddress((void**)&pwh, g_pw_h);  cudaGetSymbolAddress((void**)&pwl, g_pw_l);
    cudaGetSymbolAddress((void**)&gwh, g_gw_h);  cudaGetSymbolAddress((void**)&gwl, g_gw_l);
    cudaGetSymbolAddress((void**)&wwh, g_ww_h);  cudaGetSymbolAddress((void**)&wwl, g_ww_l);
    cudaGetSymbolAddress((void**)&thh, g_th_h);  cudaGetSymbolAddress((void**)&thl, g_th_l);
    cudaGetSymbolAddress((void**)&phh, g_ph_h);  cudaGetSymbolAddress((void**)&phl, g_ph_l);
    cudaGetSymbolAddress((void**)&gvh, g_gv_h);  cudaGetSymbolAddress((void**)&gvl, g_gv_l);
    cudaGetSymbolAddress((void**)&ath, g_at_h);  cudaGetSymbolAddress((void**)&atl, g_at_l);
    cudaGetSymbolAddress((void**)&yh,  g_y_h);   cudaGetSymbolAddress((void**)&yl,  g_y_l);
    cudaGetSymbolAddress((void**)&logits, g_logits);

    cudaFuncSetAttribute(gemm_mma<0>, cudaFuncAttributeMaxDynamicSharedMemorySize, GEMM_SMEM);
    cudaFuncSetAttribute(gemm_mma<1>, cudaFuncAttributeMaxDynamicSharedMemorySize, GEMM_SMEM);
    cudaFuncSetAttribute(gemm_mma<2>, cudaFuncAttributeMaxDynamicSharedMemorySize, GEMM_SMEM);
    cudaFuncSetAttribute(gemm_mma<3>, cudaFuncAttributeMaxDynamicSharedMemorySize, GEMM_SMEM);
    cudaFuncSetAttribute(gemm_mma<4>, cudaFuncAttributeMaxDynamicSharedMemorySize, GEMM_SMEM);

    // conversions
    transpose_split_k<<<dim3(NPIX / 32, CCH / 32, BATCH), dim3(32, 8)>>>(x, xTh, xTl);
    split_arr_k<<<256, 256>>>(theta_w, twh, twl, CI * CCH);
    split_arr_k<<<256, 256>>>(phi_w,   pwh, pwl, CI * CCH);
    split_arr_k<<<256, 256>>>(g_w,     gwh, gwl, CI * CCH);
    split_arr_k<<<256, 256>>>(w_w,     wwh, wwl, CCH * CI);

    // K1a: theta[b][n][o] = xT[b][n][:]·tw[o][:] + tb[o]  (col bias, split out)
    gemm_mma<1><<<dim3(CI / 128, NPIX / 128, BATCH), 256, GEMM_SMEM>>>(
        xTh, xTl, twh, twl, CCH, CCH, CCH, CI,
        (long)NPIX * CCH, 0, (long)NPIX * CI,
        nullptr, thh, thl, theta_b,
        nullptr, nullptr, nullptr, nullptr, nullptr, nullptr, 0);
    // K1b: phi[b][m][o]
    gemm_mma<1><<<dim3(CI / 128, NPIX / 128, BATCH), 256, GEMM_SMEM>>>(
        xTh, xTl, pwh, pwl, CCH, CCH, CCH, CI,
        (long)NPIX * CCH, 0, (long)NPIX * CI,
        nullptr, phh, phl, phi_b,
        nullptr, nullptr, nullptr, nullptr, nullptr, nullptr, 0);
    // K1c: g[b][o][n'] = gw[o][:]·xT[b][n'][:] + gb[o]  (row bias, split out)
    gemm_mma<2><<<dim3(NPIX / 128, CI / 128, BATCH), 256, GEMM_SMEM>>>(
        gwh, gwl, xTh, xTl, CCH, CCH, CCH, NPIX,
        0, (long)NPIX * CCH, (long)CI * NPIX,
        nullptr, gvh, gvl, g_b,
        nullptr, nullptr, nullptr, nullptr, nullptr, nullptr, 0);

    // K2: logits[b][n][m] = theta[b][n][:]·phi[b][m][:]  (fp32 out)
    gemm_mma<0><<<dim3(NPIX / 128, NPIX / 128, BATCH), 256, GEMM_SMEM>>>(
        thh, thl, phh, phl, CI, CI, CI, NPIX,
        (long)NPIX * CI, (long)NPIX * CI, (long)NPIX * NPIX,
        logits, nullptr, nullptr, nullptr,
        nullptr, nullptr, nullptr, nullptr, nullptr, nullptr, 0);

    // K3: softmax -> split bf16 attn
    softmax_split<<<dim3(NPIX, BATCH), 256>>>(logits, ath, atl);

    // K4: y[b][n][o] = attn[b][n][:]·g[b][o][:]  (split out)
    gemm_mma<3><<<dim3(CI / 128, NPIX / 128, BATCH), 256, GEMM_SMEM>>>(
        ath, atl, gvh, gvl, NPIX, NPIX, NPIX, CI,
        (long)NPIX * NPIX, (long)CI * NPIX, (long)NPIX * CI,
        nullptr, yh, yl, nullptr,
        nullptr, nullptr, nullptr, nullptr, nullptr, nullptr, 0);

    // K5: out[b][c][n] = BN(ww[c][:]·y[b][n][:] + wb[c]) + x[b][c][n]
    gemm_mma<4><<<dim3(NPIX / 128, CCH / 128, BATCH), 256, GEMM_SMEM>>>(
        wwh, wwl, yh, yl, CI, CI, CI, NPIX,
        0, (long)NPIX * CI, (long)CCH * NPIX,
        out, nullptr, nullptr, nullptr,
        w_b, bn_g, bn_b, bn_m, bn_v, x, (long)CCH * NPIX);
}

// round 5
// speedup vs baseline: 4.2914x; 1.3975x over previous
#include <cuda_runtime.h>
#include <cuda_bf16.h>
#include <cuda_fp16.h>
#include <cstdint>

using bf16 = __nv_bfloat16;
using f16  = __half;

// ---------------- problem constants ----------------
constexpr int  BATCH = 16;
constexpr int  CCH   = 1024;   // C
constexpr int  CI    = 256;    // inter channels
constexpr int  NPIX  = 2048;   // H*W
constexpr float BN_EPS = 1e-5f;

// ---------------- scratch (device globals) ----------------
__device__ bf16 g_xT_h[(long)BATCH * NPIX * CCH];
__device__ bf16 g_xT_l[(long)BATCH * NPIX * CCH];
__device__ f16  g_xT_f[(long)BATCH * NPIX * CCH];
__device__ bf16 g_tw_h[CI * CCH];  __device__ bf16 g_tw_l[CI * CCH];
__device__ bf16 g_pw_h[CI * CCH];  __device__ bf16 g_pw_l[CI * CCH];
__device__ f16  g_gw_f[CI * CCH];
__device__ f16  g_ww_f[CCH * CI];
__device__ bf16 g_th_h[(long)BATCH * NPIX * CI];  __device__ bf16 g_th_l[(long)BATCH * NPIX * CI];
__device__ bf16 g_ph_h[(long)BATCH * NPIX * CI];  __device__ bf16 g_ph_l[(long)BATCH * NPIX * CI];
__device__ f16  g_gv_f[(long)BATCH * CI * NPIX];
__device__ float g_logits[(long)BATCH * NPIX * NPIX];
__device__ f16  g_at_f[(long)BATCH * NPIX * NPIX];
__device__ f16  g_y_f[(long)BATCH * NPIX * CI];

// ---------------- small helpers ----------------
__device__ __forceinline__ uint32_t smem_u32(const void* p) {
    uint32_t a;
    asm("{ .reg .u64 t; cvta.to.shared.u64 t, %1; cvt.u32.u64 %0, t; }" : "=r"(a) : "l"(p));
    return a;
}
// swizzle for 64B rows: XOR bits[4:5] with row bits[1:2]
__device__ __forceinline__ uint32_t sw64(uint32_t x) { return x ^ ((x >> 3) & 0x30); }

__device__ __forceinline__ void cpa16(uint32_t dst, const void* src) {
    asm volatile("cp.async.cg.shared.global [%0], [%1], 16;" :: "r"(dst), "l"(src) : "memory");
}
__device__ __forceinline__ void cpa_commit() { asm volatile("cp.async.commit_group;" ::: "memory"); }

__device__ __forceinline__ void ldsm4(uint32_t& r0, uint32_t& r1, uint32_t& r2, uint32_t& r3,
                                      uint32_t a) {
    asm volatile("ldmatrix.sync.aligned.m8n8.x4.shared.b16 {%0,%1,%2,%3}, [%4];"
                 : "=r"(r0), "=r"(r1), "=r"(r2), "=r"(r3) : "r"(a));
}
__device__ __forceinline__ void mma_bf(float* d, const uint32_t* a, const uint32_t* b) {
    asm volatile(
        "mma.sync.aligned.m16n8k16.row.col.f32.bf16.bf16.f32 "
        "{%0,%1,%2,%3}, {%4,%5,%6,%7}, {%8,%9}, {%0,%1,%2,%3};"
        : "+f"(d[0]), "+f"(d[1]), "+f"(d[2]), "+f"(d[3])
        : "r"(a[0]), "r"(a[1]), "r"(a[2]), "r"(a[3]), "r"(b[0]), "r"(b[1]));
}
__device__ __forceinline__ void mma_fp(float* d, const uint32_t* a, const uint32_t* b) {
    asm volatile(
        "mma.sync.aligned.m16n8k16.row.col.f32.f16.f16.f32 "
        "{%0,%1,%2,%3}, {%4,%5,%6,%7}, {%8,%9}, {%0,%1,%2,%3};"
        : "+f"(d[0]), "+f"(d[1]), "+f"(d[2]), "+f"(d[3])
        : "r"(a[0]), "r"(a[1]), "r"(a[2]), "r"(a[3]), "r"(b[0]), "r"(b[1]));
}

__device__ __forceinline__ uint32_t pk2(bf16 a, bf16 b) {
    __nv_bfloat162 t = __halves2bfloat162(a, b);
    return *reinterpret_cast<uint32_t*>(&t);
}
__device__ __forceinline__ uint32_t pk2h(f16 a, f16 b) {
    __half2 t = __halves2half2(a, b);
    return *reinterpret_cast<uint32_t*>(&t);
}
__device__ __forceinline__ void split2(float v, bf16& h, bf16& l) {
    h = __float2bfloat16(v);
    l = __float2bfloat16(v - __bfloat162float(h));
}

// ================= split-bf16 3-pass GEMM (precision-critical path) =================
// D[m][n] = sum_k A[m][k]*B[n][k]; K-major split bf16 (hi+lo).
// CTA 128x128, 8 warps (2m x 4n), warp tile 64x32, K-chunk 32, 2-stage cp.async.
// EPI: 0=fp32 store; 1=split store + col bias
constexpr int STAGE_S = 4 * 8192;
constexpr int SMEM_S  = 2 * STAGE_S + 1024;

template<int EPI>
__global__ void __launch_bounds__(256, 1)
gemm_split(const bf16* __restrict__ Ah_, const bf16* __restrict__ Al_,
           const bf16* __restrict__ Bh_, const bf16* __restrict__ Bl_,
           int K, int lda, int ldb, int ldc,
           long sA, long sB, long sC,
           float* __restrict__ Cf, bf16* __restrict__ Ch, bf16* __restrict__ Cl,
           const float* __restrict__ bias)
{
    extern __shared__ char smem[];
    const uint32_t sbase = (smem_u32(smem) + 1023) & ~1023u;

    const int tid  = threadIdx.x;
    const int lane = tid & 31;
    const int wid  = tid >> 5;
    const int m0 = blockIdx.y * 128, n0 = blockIdx.x * 128, b = blockIdx.z;
    const int m_off = (wid & 1) * 64;
    const int n_off = (wid >> 1) * 32;

    const bf16* A0h = Ah_ + (long)b * sA;
    const bf16* A0l = Al_ + (long)b * sA;
    const bf16* B0h = Bh_ + (long)b * sB;
    const bf16* B0l = Bl_ + (long)b * sB;

    const int lseg = tid & 3, lrow = tid >> 2;
    auto LD = [&](int s, int k0) {
        const uint32_t st = sbase + s * STAGE_S;
#pragma unroll
        for (int rr = 0; rr < 2; rr++) {
            const int r = lrow + rr * 64;
            const uint32_t sw = sw64((uint32_t)(r * 64 + lseg * 16));
            const long ao = (long)(m0 + r) * lda + k0 + lseg * 8;
            const long bo = (long)(n0 + r) * ldb + k0 + lseg * 8;
            cpa16(st +         sw, A0h + ao);
            cpa16(st +  8192 + sw, A0l + ao);
            cpa16(st + 16384 + sw, B0h + bo);
            cpa16(st + 24576 + sw, B0l + bo);
        }
        cpa_commit();
    };

    const uint32_t swA = sw64((uint32_t)((m_off + (lane & 15)) * 64 + ((lane >> 4) & 1) * 16));
    const uint32_t swB = sw64((uint32_t)((n_off + (lane & 7) + ((lane >> 4) << 3)) * 64
                                         + ((lane >> 3) & 1) * 16));

    float d[4][4][4];
#pragma unroll
    for (int mi = 0; mi < 4; mi++)
#pragma unroll
        for (int ni = 0; ni < 4; ni++)
#pragma unroll
            for (int t = 0; t < 4; t++) d[mi][ni][t] = 0.f;

    const int nch = K >> 5;
    LD(0, 0);
    LD(1, 32);

    for (int i = 0; i < nch; i++) {
        const int s = i & 1;
        if (i + 1 < nch) asm volatile("cp.async.wait_group 1;" ::: "memory");
        else             asm volatile("cp.async.wait_group 0;" ::: "memory");
        __syncthreads();

        const uint32_t st = sbase + s * STAGE_S;
#pragma unroll
        for (int kh = 0; kh < 2; kh++) {
            const uint32_t kx = (uint32_t)kh << 5;   // XOR, not add (carry-safe)
            uint32_t aH[4][4], aL[4][4], bH[4][2], bL[4][2];
#pragma unroll
            for (int mi = 0; mi < 4; mi++) {
                ldsm4(aH[mi][0], aH[mi][1], aH[mi][2], aH[mi][3],
                      st + (swA ^ kx) + mi * 1024);
                ldsm4(aL[mi][0], aL[mi][1], aL[mi][2], aL[mi][3],
                      st + 8192 + (swA ^ kx) + mi * 1024);
            }
#pragma unroll
            for (int np = 0; np < 2; np++) {
                ldsm4(bH[np*2][0], bH[np*2][1], bH[np*2+1][0], bH[np*2+1][1],
                      st + 16384 + (swB ^ kx) + np * 1024);
                ldsm4(bL[np*2][0], bL[np*2][1], bL[np*2+1][0], bL[np*2+1][1],
                      st + 24576 + (swB ^ kx) + np * 1024);
            }
#pragma unroll
            for (int mi = 0; mi < 4; mi++)
#pragma unroll
                for (int ni = 0; ni < 4; ni++) {
                    mma_bf(d[mi][ni], aH[mi], bH[ni]);
                    mma_bf(d[mi][ni], aH[mi], bL[ni]);
                    mma_bf(d[mi][ni], aL[mi], bH[ni]);
                }
        }
        __syncthreads();
        if (i + 2 < nch) LD(s, (i + 2) * 32);
    }

    const int rsub = lane >> 2;
    const int csub = (lane & 3) * 2;
#pragma unroll
    for (int mi = 0; mi < 4; mi++) {
#pragma unroll
        for (int h = 0; h < 2; h++) {
            const int m = m0 + m_off + mi * 16 + rsub + h * 8;
#pragma unroll
            for (int ni = 0; ni < 4; ni++) {
                const int col = n0 + n_off + ni * 8 + csub;
                float v0 = d[mi][ni][2 * h];
                float v1 = d[mi][ni][2 * h + 1];
                if (EPI == 1) { v0 += bias[col]; v1 += bias[col + 1]; }
                const long base = (long)b * sC + (long)m * ldc + col;
                if (EPI == 0) {
                    *(float2*)(Cf + base) = make_float2(v0, v1);
                } else {
                    bf16 h0, l0, h1, l1;
                    split2(v0, h0, l0);
                    split2(v1, h1, l1);
                    *(uint32_t*)(Ch + base) = pk2(h0, h1);
                    *(uint32_t*)(Cl + base) = pk2(l0, l1);
                }
            }
        }
    }
}

// ================= single-pass fp16 GEMM (linear / post-softmax path) =================
// EPI: 2 = row bias + f16 store; 3 = f16 store; 4 = BN+residual fp32 store
constexpr int STAGE_H = 2 * 8192;
constexpr int SMEM_H  = 2 * STAGE_H + 1024;

template<int EPI>
__global__ void __launch_bounds__(256, 2)
gemm_half(const f16* __restrict__ A_, const f16* __restrict__ B_,
          int K, int lda, int ldb, int ldc,
          long sA, long sB, long sC,
          float* __restrict__ Cf, f16* __restrict__ Ch,
          const float* __restrict__ bias,
          const float* __restrict__ wb,  const float* __restrict__ gma,
          const float* __restrict__ bta, const float* __restrict__ mean,
          const float* __restrict__ var, const float* __restrict__ resid, long sRes)
{
    extern __shared__ char smem[];
    const uint32_t sbase = (smem_u32(smem) + 1023) & ~1023u;

    const int tid  = threadIdx.x;
    const int lane = tid & 31;
    const int wid  = tid >> 5;
    const int m0 = blockIdx.y * 128, n0 = blockIdx.x * 128, b = blockIdx.z;
    const int m_off = (wid & 1) * 64;
    const int n_off = (wid >> 1) * 32;

    const f16* A0 = A_ + (long)b * sA;
    const f16* B0 = B_ + (long)b * sB;

    const int lseg = tid & 3, lrow = tid >> 2;
    auto LD = [&](int s, int k0) {
        const uint32_t st = sbase + s * STAGE_H;
#pragma unroll
        for (int rr = 0; rr < 2; rr++) {
            const int r = lrow + rr * 64;
            const uint32_t sw = sw64((uint32_t)(r * 64 + lseg * 16));
            cpa16(st +        sw, A0 + (long)(m0 + r) * lda + k0 + lseg * 8);
            cpa16(st + 8192 + sw, B0 + (long)(n0 + r) * ldb + k0 + lseg * 8);
        }
        cpa_commit();
    };

    const uint32_t swA = sw64((uint32_t)((m_off + (lane & 15)) * 64 + ((lane >> 4) & 1) * 16));
    const uint32_t swB = sw64((uint32_t)((n_off + (lane & 7) + ((lane >> 4) << 3)) * 64
                                         + ((lane >> 3) & 1) * 16));

    float d[4][4][4];
#pragma unroll
    for (int mi = 0; mi < 4; mi++)
#pragma unroll
        for (int ni = 0; ni < 4; ni++)
#pragma unroll
            for (int t = 0; t < 4; t++) d[mi][ni][t] = 0.f;

    const int nch = K >> 5;
    LD(0, 0);
    LD(1, 32);

    for (int i = 0; i < nch; i++) {
        const int s = i & 1;
        if (i + 1 < nch) asm volatile("cp.async.wait_group 1;" ::: "memory");
        else             asm volatile("cp.async.wait_group 0;" ::: "memory");
        __syncthreads();

        const uint32_t st = sbase + s * STAGE_H;
#pragma unroll
        for (int kh = 0; kh < 2; kh++) {
            const uint32_t kx = (uint32_t)kh << 5;
            uint32_t a[4][4], bb[4][2];
#pragma unroll
            for (int mi = 0; mi < 4; mi++)
                ldsm4(a[mi][0], a[mi][1], a[mi][2], a[mi][3],
                      st + (swA ^ kx) + mi * 1024);
#pragma unroll
            for (int np = 0; np < 2; np++)
                ldsm4(bb[np*2][0], bb[np*2][1], bb[np*2+1][0], bb[np*2+1][1],
                      st + 8192 + (swB ^ kx) + np * 1024);
#pragma unroll
            for (int mi = 0; mi < 4; mi++)
#pragma unroll
                for (int ni = 0; ni < 4; ni++)
                    mma_fp(d[mi][ni], a[mi], bb[ni]);
        }
        __syncthreads();
        if (i + 2 < nch) LD(s, (i + 2) * 32);
    }

    const int rsub = lane >> 2;
    const int csub = (lane & 3) * 2;
#pragma unroll
    for (int mi = 0; mi < 4; mi++) {
#pragma unroll
        for (int h = 0; h < 2; h++) {
            const int m = m0 + m_off + mi * 16 + rsub + h * 8;
            float inv = 1.f, add = 0.f, post = 0.f;
            if (EPI == 2) add = bias[m];
            if (EPI == 4) {
                inv  = gma[m] * rsqrtf(var[m] + BN_EPS);
                add  = wb[m] - mean[m];
                post = bta[m];
            }
#pragma unroll
            for (int ni = 0; ni < 4; ni++) {
                const int col = n0 + n_off + ni * 8 + csub;
                float v0 = d[mi][ni][2 * h];
                float v1 = d[mi][ni][2 * h + 1];
                const long base = (long)b * sC + (long)m * ldc + col;
                if (EPI == 4) {
                    float2 r = *(const float2*)(resid + (long)b * sRes + (long)m * ldc + col);
                    *(float2*)(Cf + base) = make_float2((v0 + add) * inv + post + r.x,
                                                        (v1 + add) * inv + post + r.y);
                } else {
                    if (EPI == 2) { v0 += add; v1 += add; }
                    *(uint32_t*)(Ch + base) = pk2h(__float2half(v0), __float2half(v1));
                }
            }
        }
    }
}

// ---------------- conversion kernels ----------------
__global__ void transpose_split_k(const float* __restrict__ x,
                                  bf16* __restrict__ oh, bf16* __restrict__ ol,
                                  f16* __restrict__ of)
{
    __shared__ float t[32][33];
    const int b = blockIdx.z;
    const int n0 = blockIdx.x * 32, c0 = blockIdx.y * 32;
    const int tx = threadIdx.x, ty = threadIdx.y;
    const float* xp = x + (long)b * CCH * NPIX;
#pragma unroll
    for (int i = 0; i < 4; i++)
        t[ty + 8*i][tx] = xp[(long)(c0 + ty + 8*i) * NPIX + n0 + tx];
    __syncthreads();
    bf16* ohp = oh + (long)b * NPIX * CCH;
    bf16* olp = ol + (long)b * NPIX * CCH;
    f16*  ofp = of + (long)b * NPIX * CCH;
#pragma unroll
    for (int i = 0; i < 4; i++) {
        const float vv = t[tx][ty + 8*i];
        const long idx = (long)(n0 + ty + 8*i) * CCH + c0 + tx;
        bf16 h, l; split2(vv, h, l);
        ohp[idx] = h; olp[idx] = l;
        ofp[idx] = __float2half(vv);
    }
}

__global__ void split_arr_k(const float* __restrict__ s, bf16* __restrict__ h,
                            bf16* __restrict__ l, int n)
{
    for (int i = blockIdx.x * blockDim.x + threadIdx.x; i < n; i += gridDim.x * blockDim.x) {
        bf16 hh, ll; split2(s[i], hh, ll);
        h[i] = hh; l[i] = ll;
    }
}

__global__ void conv_half_k(const float* __restrict__ s, f16* __restrict__ d, int n)
{
    for (int i = blockIdx.x * blockDim.x + threadIdx.x; i < n; i += gridDim.x * blockDim.x)
        d[i] = __float2half(s[i]);
}

// ---------------- row softmax -> fp16 ----------------
__global__ void softmax_half(const float* __restrict__ L, f16* __restrict__ A)
{
    const long row = (long)blockIdx.y * gridDim.x + blockIdx.x;
    const float* p = L + row * (long)NPIX;
    const int tid = threadIdx.x, lane = tid & 31, warp = tid >> 5;

    float4 u0 = *(const float4*)(p + tid * 8);
    float4 u1 = *(const float4*)(p + tid * 8 + 4);
    float v[8] = {u0.x, u0.y, u0.z, u0.w, u1.x, u1.y, u1.z, u1.w};

    __shared__ float red[8];
    float mx = v[0];
#pragma unroll
    for (int i = 1; i < 8; i++) mx = fmaxf(mx, v[i]);
#pragma unroll
    for (int o = 16; o; o >>= 1) mx = fmaxf(mx, __shfl_xor_sync(0xffffffffu, mx, o));
    if (lane == 0) red[warp] = mx;
    __syncthreads();
    mx = red[0];
#pragma unroll
    for (int w = 1; w < 8; w++) mx = fmaxf(mx, red[w]);

    float s = 0.f;
#pragma unroll
    for (int i = 0; i < 8; i++) { v[i] = __expf(v[i] - mx); s += v[i]; }
#pragma unroll
    for (int o = 16; o; o >>= 1) s += __shfl_xor_sync(0xffffffffu, s, o);
    __syncthreads();
    if (lane == 0) red[warp] = s;
    __syncthreads();
    s = red[0];
#pragma unroll
    for (int w = 1; w < 8; w++) s += red[w];

    const float r = 1.0f / s;
    uint32_t w4[4];
#pragma unroll
    for (int t = 0; t < 4; t++)
        w4[t] = pk2h(__float2half(v[2*t] * r), __float2half(v[2*t+1] * r));
    *(uint4*)(A + row * (long)NPIX + tid * 8) = make_uint4(w4[0], w4[1], w4[2], w4[3]);
}

// ---------------- launch ----------------
extern "C" void kernel_launch(void* const* d_in, const int* in_sizes, int n_in,
                              void* d_out, int out_size)
{
    const float* x       = (const float*)d_in[0];
    const float* theta_w = (const float*)d_in[1];
    const float* theta_b = (const float*)d_in[2];
    const float* phi_w   = (const float*)d_in[3];
    const float* phi_b   = (const float*)d_in[4];
    const float* g_w     = (const float*)d_in[5];
    const float* g_b     = (const float*)d_in[6];
    const float* w_w     = (const float*)d_in[7];
    const float* w_b     = (const float*)d_in[8];
    const float* bn_g    = (const float*)d_in[9];
    const float* bn_b    = (const float*)d_in[10];
    const float* bn_m    = (const float*)d_in[11];
    const float* bn_v    = (const float*)d_in[12];
    float* out = (float*)d_out;

    bf16 *xTh, *xTl, *twh, *twl, *pwh, *pwl, *thh, *thl, *phh, *phl;
    f16 *xTf, *gwf, *wwf, *gvf, *atf, *yf;
    float* logits;
    cudaGetSymbolAddress((void**)&xTh, g_xT_h);  cudaGetSymbolAddress((void**)&xTl, g_xT_l);
    cudaGetSymbolAddress((void**)&xTf, g_xT_f);
    cudaGetSymbolAddress((void**)&twh, g_tw_h);  cudaGetSymbolAddress((void**)&twl, g_tw_l);
    cudaGetSymbolAddress((void**)&pwh, g_pw_h);  cudaGetSymbolAddress((void**)&pwl, g_pw_l);
    cudaGetSymbolAddress((void**)&gwf, g_gw_f);
    cudaGetSymbolAddress((void**)&wwf, g_ww_f);
    cudaGetSymbolAddress((void**)&thh, g_th_h);  cudaGetSymbolAddress((void**)&thl, g_th_l);
    cudaGetSymbolAddress((void**)&phh, g_ph_h);  cudaGetSymbolAddress((void**)&phl, g_ph_l);
    cudaGetSymbolAddress((void**)&gvf, g_gv_f);
    cudaGetSymbolAddress((void**)&atf, g_at_f);
    cudaGetSymbolAddress((void**)&yf,  g_y_f);
    cudaGetSymbolAddress((void**)&logits, g_logits);

    cudaFuncSetAttribute(gemm_split<0>, cudaFuncAttributeMaxDynamicSharedMemorySize, SMEM_S);
    cudaFuncSetAttribute(gemm_split<1>, cudaFuncAttributeMaxDynamicSharedMemorySize, SMEM_S);
    cudaFuncSetAttribute(gemm_half<2>, cudaFuncAttributeMaxDynamicSharedMemorySize, SMEM_H);
    cudaFuncSetAttribute(gemm_half<3>, cudaFuncAttributeMaxDynamicSharedMemorySize, SMEM_H);
    cudaFuncSetAttribute(gemm_half<4>, cudaFuncAttributeMaxDynamicSharedMemorySize, SMEM_H);

    // conversions
    transpose_split_k<<<dim3(NPIX / 32, CCH / 32, BATCH), dim3(32, 8)>>>(x, xTh, xTl, xTf);
    split_arr_k<<<256, 256>>>(theta_w, twh, twl, CI * CCH);
    split_arr_k<<<256, 256>>>(phi_w,   pwh, pwl, CI * CCH);
    conv_half_k<<<256, 256>>>(g_w, gwf, CI * CCH);
    conv_half_k<<<256, 256>>>(w_w, wwf, CCH * CI);

    // K1a: theta[b][n][o] (split bf16, 3-pass) + col bias
    gemm_split<1><<<dim3(CI / 128, NPIX / 128, BATCH), 256, SMEM_S>>>(
        xTh, xTl, twh, twl, CCH, CCH, CCH, CI,
        (long)NPIX * CCH, 0, (long)NPIX * CI,
        nullptr, thh, thl, theta_b);
    // K1b: phi[b][m][o]
    gemm_split<1><<<dim3(CI / 128, NPIX / 128, BATCH), 256, SMEM_S>>>(
        xTh, xTl, pwh, pwl, CCH, CCH, CCH, CI,
        (long)NPIX * CCH, 0, (long)NPIX * CI,
        nullptr, phh, phl, phi_b);
    // K1c: g[b][o][n'] = gw[o][:]·xT[b][n'][:] + gb[o]  (fp16 single, row bias)
    gemm_half<2><<<dim3(NPIX / 128, CI / 128, BATCH), 256, SMEM_H>>>(
        gwf, xTf, CCH, CCH, CCH, NPIX,
        0, (long)NPIX * CCH, (long)CI * NPIX,
        nullptr, gvf, g_b,
        nullptr, nullptr, nullptr, nullptr, nullptr, nullptr, 0);

    // K2: logits = theta·phi^T  (split bf16 3-pass, fp32 out)
    gemm_split<0><<<dim3(NPIX / 128, NPIX / 128, BATCH), 256, SMEM_S>>>(
        thh, thl, phh, phl, CI, CI, CI, NPIX,
        (long)NPIX * CI, (long)NPIX * CI, (long)NPIX * NPIX,
        logits, nullptr, nullptr, nullptr);

    // K3: softmax -> fp16 attn
    softmax_half<<<dim3(NPIX, BATCH), 256>>>(logits, atf);

    // K4: y[b][n][o] = attn[b][n][:]·g[b][o][:]  (fp16 single)
    gemm_half<3><<<dim3(CI / 128, NPIX / 128, BATCH), 256, SMEM_H>>>(
        atf, gvf, NPIX, NPIX, NPIX, CI,
        (long)NPIX * NPIX, (long)CI * NPIX, (long)NPIX * CI,
        nullptr, yf, nullptr,
        nullptr, nullptr, nullptr, nullptr, nullptr, nullptr, 0);

    // K5: out = BN(ww·y + wb) + x  (fp16 single, fp32 out)
    gemm_half<4><<<dim3(NPIX / 128, CCH / 128, BATCH), 256, SMEM_H>>>(
        wwf, yf, CI, CI, CI, NPIX,
        0, (long)NPIX * CI, (long)CCH * NPIX,
        out, nullptr, nullptr,
        w_b, bn_g, bn_b, bn_m, bn_v, x, (long)CCH * NPIX);
}